// round 1
// baseline (speedup 1.0000x reference)
#include <cuda_runtime.h>
#include <cuda_bf16.h>

// LocalitySensitiveHashing_29111288333011
//
// Mathematical collapse of the reference:
//   qh, kh = sign(...)  ->  elements in {-1, 0, +1}
//   einsum('bqhk,bkhk->bhqk') has no summed index (repeated k = diagonal),
//   so sim[b,h,q,k] = qh[b,q,h,k] * kh[b,k,h,k]  in {-1, 0, +1}.
//   sim = sim / hash_bits (HB=2048), then mean over H=8 heads:
//       |sim[b,q,k]| <= 1/HB = 4.88e-4
//   Threshold is 0.3  ->  (sim > 0.3) is False for EVERY element, for ANY
//   input (requires only HB > 1/0.3). Output is exactly zeros([2,2048,2048]).
//
// Therefore the optimal kernel is a pure zero-fill of d_out (32 MiB),
// bounded by HBM store bandwidth only. No inputs are read.

__global__ void lsh_zero4_kernel(float4* __restrict__ out, long long n4) {
    long long i = (long long)blockIdx.x * blockDim.x + threadIdx.x;
    if (i < n4) {
        out[i] = make_float4(0.0f, 0.0f, 0.0f, 0.0f);
    }
}

__global__ void lsh_zero1_kernel(float* __restrict__ out, long long n) {
    long long i = (long long)blockIdx.x * blockDim.x + threadIdx.x;
    if (i < n) {
        out[i] = 0.0f;
    }
}

extern "C" void kernel_launch(void* const* d_in, const int* in_sizes, int n_in,
                              void* d_out, int out_size) {
    (void)d_in; (void)in_sizes; (void)n_in;

    float* out = (float*)d_out;
    long long n  = (long long)out_size;     // expected 2*2048*2048 = 8388608
    long long n4 = n >> 2;                  // float4 count
    long long rem = n - (n4 << 2);

    if (n4 > 0) {
        const int threads = 256;
        long long blocks = (n4 + threads - 1) / threads;   // 8192 blocks for this shape
        lsh_zero4_kernel<<<(unsigned int)blocks, threads>>>((float4*)out, n4);
    }
    if (rem > 0) {
        lsh_zero1_kernel<<<1, 32>>>(out + (n4 << 2), rem);
    }
}

// round 2
// speedup vs baseline: 1.0332x; 1.0332x over previous
#include <cuda_runtime.h>
#include <cuda_bf16.h>

// LocalitySensitiveHashing_29111288333011
//
// Mathematical collapse of the reference (holds for ALL inputs, not this seed):
//   qh, kh = sign(...)  ->  elements in {-1, 0, +1}
//   einsum('bqhk,bkhk->bhqk') has no summed index (repeated k = diagonal),
//   so sim[b,h,q,k] = qh[b,q,h,k] * kh[b,k,h,k]  in {-1, 0, +1}.
//   sim /= hash_bits (HB=2048), then mean over H=8 heads:
//       |sim[b,q,k]| <= 1/HB = 4.88e-4  <  SIM_THRESHOLD = 0.3
//   -> (sim > 0.3) is identically False. Output == zeros([2,2048,2048]).
//
// So the kernel is a pure zero-fill of d_out (32 MiB). The 32 MiB target fits
// in GB300's ~126 MB L2, so the ceiling is the LTS write cap (~6300 B/cyc),
// not HBM. R1 was issue/launch-bound (1 STG.128 per thread, issue=20.9%);
// this version stores V=8 float4 per thread to amortize warp setup/retire.

#ifndef ZF_V
#define ZF_V 8          // float4 stores per thread
#endif
#define ZF_THREADS 256

__global__ __launch_bounds__(ZF_THREADS)
void lsh_zero_kernel(float4* __restrict__ out, long long n4) {
    const float4 z = make_float4(0.0f, 0.0f, 0.0f, 0.0f);
    const long long tile = (long long)ZF_THREADS * ZF_V;
    long long base = (long long)blockIdx.x * tile + threadIdx.x;

    if (base + (long long)(ZF_V - 1) * ZF_THREADS < n4) {
        // full tile: no per-store bounds checks, 8 back-to-back STG.128
        #pragma unroll
        for (int j = 0; j < ZF_V; j++) {
            out[base + (long long)j * ZF_THREADS] = z;
        }
    } else {
        #pragma unroll
        for (int j = 0; j < ZF_V; j++) {
            long long i = base + (long long)j * ZF_THREADS;
            if (i < n4) out[i] = z;
        }
    }
}

__global__ void lsh_zero_tail_kernel(float* __restrict__ out, long long n) {
    long long i = (long long)blockIdx.x * blockDim.x + threadIdx.x;
    if (i < n) out[i] = 0.0f;
}

extern "C" void kernel_launch(void* const* d_in, const int* in_sizes, int n_in,
                              void* d_out, int out_size) {
    (void)d_in; (void)in_sizes; (void)n_in;

    float* out = (float*)d_out;
    long long n  = (long long)out_size;   // 2*2048*2048 = 8388608 for this problem
    long long n4 = n >> 2;                // float4 count (2,097,152)
    long long rem = n - (n4 << 2);        // 0 here

    if (n4 > 0) {
        const long long tile = (long long)ZF_THREADS * ZF_V;   // 2048 float4 / block
        long long blocks = (n4 + tile - 1) / tile;             // 1024 blocks
        lsh_zero_kernel<<<(unsigned int)blocks, ZF_THREADS>>>((float4*)out, n4);
    }
    if (rem > 0) {
        lsh_zero_tail_kernel<<<1, 32>>>(out + (n4 << 2), rem);
    }
}